// round 2
// baseline (speedup 1.0000x reference)
#include <cuda_runtime.h>
#include <cuda_bf16.h>
#include <stdint.h>

// loss = [ sum_{b,c,d} erfc(y) + 2*B*D - 2*sum_{b,d} erfc(y[b,label_b,d]) ] / (B*C)
// y = |W[c,d]-mu[b,d]| / (sqrt(2)*(std[b,d]+1e-8))

__device__ double g_acc;

#define BT 8          // batches per CTA (= warps per CTA)
#define CT 8          // classes per CTA (smem tile)
#define DCONST 512    // head dim (fixed for this problem)

// Abramowitz & Stegun 7.1.26 erfc for x >= 0, max abs err 1.5e-7
__device__ __forceinline__ float erfc_pos(float x) {
    float t = __fdividef(1.0f, fmaf(0.3275911f, x, 1.0f));
    float p = 1.061405429f;
    p = fmaf(p, t, -1.453152027f);
    p = fmaf(p, t,  1.421413741f);
    p = fmaf(p, t, -0.284496736f);
    p = fmaf(p, t,  0.254829592f);
    p *= t;
    float e = __expf(-x * x);
    return p * e;
}

__global__ void zero_kernel() { g_acc = 0.0; }

__global__ __launch_bounds__(BT * 32, 8)
void erfc_main_kernel(const float* __restrict__ mu,
                      const float* __restrict__ stdv,
                      const float* __restrict__ w) {
    __shared__ float sw[CT * DCONST];
    __shared__ float wsum[BT];

    const int c0 = blockIdx.x * CT;
    const int b0 = blockIdx.y * BT;

    // Cooperative load of the weight tile: CT full rows are contiguous in gmem.
    {
        const float4* src = reinterpret_cast<const float4*>(w + (size_t)c0 * DCONST);
        float4* dst = reinterpret_cast<float4*>(sw);
        for (int i = threadIdx.x; i < CT * DCONST / 4; i += blockDim.x)
            dst[i] = src[i];
    }
    __syncthreads();

    const int warp = threadIdx.x >> 5;
    const int lane = threadIdx.x & 31;
    const int b = b0 + warp;

    // Preload this warp's mu / inv-scale into registers.
    // Lane handles d = 2*lane + 64*i, i = 0..7 (float2 granularity, coalesced).
    float2 m2[8], v2[8];
    {
        const float2* mup = reinterpret_cast<const float2*>(mu + (size_t)b * DCONST);
        const float2* sp  = reinterpret_cast<const float2*>(stdv + (size_t)b * DCONST);
#pragma unroll
        for (int i = 0; i < 8; i++) {
            m2[i] = mup[lane + 32 * i];
            float2 s = sp[lane + 32 * i];
            v2[i].x = __fdividef(1.0f, 1.41421356237f * (s.x + 1e-8f));
            v2[i].y = __fdividef(1.0f, 1.41421356237f * (s.y + 1e-8f));
        }
    }

    float acc = 0.0f;
#pragma unroll
    for (int c = 0; c < CT; c++) {
        const float2* wr = reinterpret_cast<const float2*>(sw + c * DCONST);
#pragma unroll
        for (int i = 0; i < 8; i++) {
            float2 ww = wr[lane + 32 * i];
            float y0 = fabsf(ww.x - m2[i].x) * v2[i].x;
            float y1 = fabsf(ww.y - m2[i].y) * v2[i].y;
            acc += erfc_pos(y0);
            acc += erfc_pos(y1);
        }
    }

    // Warp reduce
#pragma unroll
    for (int o = 16; o > 0; o >>= 1)
        acc += __shfl_xor_sync(0xFFFFFFFFu, acc, o);
    if (lane == 0) wsum[warp] = acc;
    __syncthreads();

    if (threadIdx.x == 0) {
        float s = 0.0f;
#pragma unroll
        for (int i = 0; i < BT; i++) s += wsum[i];
        atomicAdd(&g_acc, (double)s);
    }
}

// Correction: subtract 2 * erfc(y[b, label_b, d]) summed over d, per batch.
// label is int32 on device: JAX with x64 disabled silently downcasts
// jnp.int64 -> int32 in setup_inputs.
__global__ void label_kernel(const float* __restrict__ mu,
                             const float* __restrict__ stdv,
                             const float* __restrict__ w,
                             const int* __restrict__ label,
                             int C, int D) {
    const int b = blockIdx.x;
    int l = label[b];
    // Defensive clamp: never dereference out of bounds even if dtype assumption
    // is wrong (would then show as rel_err, not an illegal access).
    if (l < 0) l = 0;
    if (l >= C) l = C - 1;
    const float* wr = w + (size_t)l * D;
    const float* mr = mu + (size_t)b * D;
    const float* sr = stdv + (size_t)b * D;

    float acc = 0.0f;
    for (int d = threadIdx.x; d < D; d += blockDim.x) {
        float iv = __fdividef(1.0f, 1.41421356237f * (sr[d] + 1e-8f));
        float y = fabsf(wr[d] - mr[d]) * iv;
        acc += erfc_pos(y);
    }
#pragma unroll
    for (int o = 16; o > 0; o >>= 1)
        acc += __shfl_xor_sync(0xFFFFFFFFu, acc, o);

    __shared__ float wsum[8];
    const int warp = threadIdx.x >> 5;
    const int lane = threadIdx.x & 31;
    if (lane == 0) wsum[warp] = acc;
    __syncthreads();
    if (threadIdx.x == 0) {
        float s = 0.0f;
        int nw = (blockDim.x + 31) >> 5;
        for (int i = 0; i < nw; i++) s += wsum[i];
        atomicAdd(&g_acc, -2.0 * (double)s);
    }
}

__global__ void finalize_kernel(float* __restrict__ out, int B, int C, int D) {
    double loss = (g_acc + 2.0 * (double)B * (double)D) / ((double)B * (double)C);
    out[0] = (float)loss;
}

extern "C" void kernel_launch(void* const* d_in, const int* in_sizes, int n_in,
                              void* d_out, int out_size) {
    const float* mu    = (const float*)d_in[0];
    const float* stdv  = (const float*)d_in[1];
    const float* w     = (const float*)d_in[2];
    const int*   label = (const int*)d_in[3];

    const int B = in_sizes[3];            // 128
    const int D = in_sizes[0] / B;        // 512
    const int C = in_sizes[2] / D;        // 1000

    zero_kernel<<<1, 1>>>();

    dim3 grid(C / CT, B / BT);            // (125, 16)
    erfc_main_kernel<<<grid, BT * 32>>>(mu, stdv, w);

    label_kernel<<<B, 256>>>(mu, stdv, w, label, C, D);

    finalize_kernel<<<1, 1>>>((float*)d_out, B, C, D);
}

// round 3
// speedup vs baseline: 2.5621x; 2.5621x over previous
#include <cuda_runtime.h>
#include <cuda_bf16.h>
#include <stdint.h>

// loss = [ sum_{b,c,d} erfc(y) + 2*B*D - 2*sum_{b,d} erfc(y[b,label_b,d]) ] / (B*C)
// y = |W[c,d]-mu[b,d]| / (sqrt(2)*(std[b,d]+1e-8))
//
// erfc via A&S 7.1.25 (3-term, |err| <= 2.5e-5):
//   erfc(x) = (a1*t + a2*t^2 + a3*t^3) * exp(-x^2),  t = 1/(1+p*x)
// with per-(b,d) prefolded constants so the inner loop is pure f32x2:
//   negm = -mu
//   aiv  = p * iv            (t-denominator = fma(aiv, |d|, 1))
//   ivl  = -log2(e) * iv^2   (exp arg for ex2: d^2 * ivl)
//   iv   = 1/(sqrt(2)*(std+1e-8))

#define BT 8          // batches per CTA (= warps)
#define CT 8          // classes per CTA (smem tile)
#define DCONST 512
#define CBLK 125      // C / CT
#define NPART ((CBLK + 1) * 16)   // 2016 partial slots, all overwritten each call

__device__ float g_partials[NPART];

// ---------- f32x2 / MUFU primitives ----------
__device__ __forceinline__ uint64_t f2add(uint64_t a, uint64_t b) {
    uint64_t r; asm("add.rn.f32x2 %0,%1,%2;" : "=l"(r) : "l"(a), "l"(b)); return r;
}
__device__ __forceinline__ uint64_t f2mul(uint64_t a, uint64_t b) {
    uint64_t r; asm("mul.rn.f32x2 %0,%1,%2;" : "=l"(r) : "l"(a), "l"(b)); return r;
}
__device__ __forceinline__ uint64_t f2fma(uint64_t a, uint64_t b, uint64_t c) {
    uint64_t r; asm("fma.rn.f32x2 %0,%1,%2,%3;" : "=l"(r) : "l"(a), "l"(b), "l"(c)); return r;
}
__device__ __forceinline__ void unpk(uint64_t v, float& lo, float& hi) {
    asm("mov.b64 {%0,%1}, %2;" : "=f"(lo), "=f"(hi) : "l"(v));
}
__device__ __forceinline__ uint64_t pk(float lo, float hi) {
    uint64_t v; asm("mov.b64 %0, {%1,%2};" : "=l"(v) : "f"(lo), "f"(hi)); return v;
}
__device__ __forceinline__ uint64_t dup2(float v) {
    uint32_t u = __float_as_uint(v); return ((uint64_t)u << 32) | u;
}
__device__ __forceinline__ float rcp_f(float x) {
    float r; asm("rcp.approx.ftz.f32 %0,%1;" : "=f"(r) : "f"(x)); return r;
}
__device__ __forceinline__ float ex2_f(float x) {
    float r; asm("ex2.approx.ftz.f32 %0,%1;" : "=f"(r) : "f"(x)); return r;
}

#define AS_P  0.47047f
#define AS_A1 0.3480242f
#define AS_A2 (-0.0958798f)
#define AS_A3 0.7478556f
#define NLOG2E (-1.4426950408889634f)
#define ABS2MASK 0x7FFFFFFF7FFFFFFFULL

// erfc of two elements, accumulated into acc (f32x2 lanes).
__device__ __forceinline__ void erfc2_acc(uint64_t w2, uint64_t nm, uint64_t ai,
                                          uint64_t il, uint64_t& acc) {
    const uint64_t ONE2 = dup2(1.0f);
    const uint64_t A1 = dup2(AS_A1), A2 = dup2(AS_A2), A3 = dup2(AS_A3);
    uint64_t d  = f2add(w2, nm);                 // w - mu
    uint64_t ad = d & ABS2MASK;                  // |d|  (ALU pipe)
    uint64_t dd = f2mul(d, d);                   // d^2
    uint64_t ea = f2mul(dd, il);                 // -log2e * x^2
    uint64_t dn = f2fma(ai, ad, ONE2);           // 1 + p*x
    float dn0, dn1, ea0, ea1;
    unpk(dn, dn0, dn1);
    unpk(ea, ea0, ea1);
    float t0 = rcp_f(dn0), t1 = rcp_f(dn1);      // MUFU.RCP
    float e0 = ex2_f(ea0), e1 = ex2_f(ea1);      // MUFU.EX2
    uint64_t t2 = pk(t0, t1);
    uint64_t e2 = pk(e0, e1);
    uint64_t p = f2fma(A3, t2, A2);
    p = f2fma(p, t2, A1);
    uint64_t pt = f2mul(p, t2);
    acc = f2fma(pt, e2, acc);
}

// Preload one warp's per-(b,d) constants. Lane owns float4 units lane+32*i, i=0..3
// (elements 4u..4u+3), stored as f32x2 pairs [2i] and [2i+1].
__device__ __forceinline__ void preload_bd(const float* __restrict__ mu,
                                           const float* __restrict__ stdv,
                                           int b, int lane,
                                           uint64_t* nm, uint64_t* ai, uint64_t* il) {
    const float4* mu4 = reinterpret_cast<const float4*>(mu + (size_t)b * DCONST);
    const float4* sd4 = reinterpret_cast<const float4*>(stdv + (size_t)b * DCONST);
#pragma unroll
    for (int i = 0; i < 4; i++) {
        float4 m = mu4[lane + 32 * i];
        float4 s = sd4[lane + 32 * i];
        float ivx = rcp_f(1.41421356237f * (s.x + 1e-8f));
        float ivy = rcp_f(1.41421356237f * (s.y + 1e-8f));
        float ivz = rcp_f(1.41421356237f * (s.z + 1e-8f));
        float ivw = rcp_f(1.41421356237f * (s.w + 1e-8f));
        nm[2 * i]     = pk(-m.x, -m.y);
        nm[2 * i + 1] = pk(-m.z, -m.w);
        ai[2 * i]     = pk(AS_P * ivx, AS_P * ivy);
        ai[2 * i + 1] = pk(AS_P * ivz, AS_P * ivw);
        il[2 * i]     = pk(NLOG2E * ivx * ivx, NLOG2E * ivy * ivy);
        il[2 * i + 1] = pk(NLOG2E * ivz * ivz, NLOG2E * ivw * ivw);
    }
}

__global__ __launch_bounds__(BT * 32, 2)
void erfc_main_kernel(const float* __restrict__ mu,
                      const float* __restrict__ stdv,
                      const float* __restrict__ w,
                      const int* __restrict__ label) {
    __shared__ float sw[CT * DCONST];
    __shared__ float wsum[BT];

    const int warp = threadIdx.x >> 5;
    const int lane = threadIdx.x & 31;
    const int b0 = blockIdx.y * BT;
    const int b = b0 + warp;
    const bool is_label_cta = (blockIdx.x == CBLK);

    if (!is_label_cta) {
        const int c0 = blockIdx.x * CT;
        const float4* src = reinterpret_cast<const float4*>(w + (size_t)c0 * DCONST);
        float4* dst = reinterpret_cast<float4*>(sw);
        for (int i = threadIdx.x; i < CT * DCONST / 4; i += blockDim.x)
            dst[i] = src[i];
    }

    uint64_t nm[8], ai[8], il[8];
    preload_bd(mu, stdv, b, lane, nm, ai, il);

    if (!is_label_cta) __syncthreads();

    uint64_t acc = 0;  // (0.0f, 0.0f)

    if (!is_label_cta) {
        const ulonglong2* sw2 = reinterpret_cast<const ulonglong2*>(sw);
#pragma unroll
        for (int c = 0; c < CT; c++) {
#pragma unroll
            for (int i = 0; i < 4; i++) {
                ulonglong2 ww = sw2[c * (DCONST / 4) + lane + 32 * i];
                erfc2_acc(ww.x, nm[2 * i],     ai[2 * i],     il[2 * i],     acc);
                erfc2_acc(ww.y, nm[2 * i + 1], ai[2 * i + 1], il[2 * i + 1], acc);
            }
        }
    } else {
        // Label correction: warp handles batch b, row = label[b], weight from gmem.
        int l = label[b];
        if (l < 0) l = 0;
        if (l >= CBLK * CT) l = CBLK * CT - 1;
        const ulonglong2* wr2 = reinterpret_cast<const ulonglong2*>(w + (size_t)l * DCONST);
#pragma unroll
        for (int i = 0; i < 4; i++) {
            ulonglong2 ww = wr2[lane + 32 * i];
            erfc2_acc(ww.x, nm[2 * i],     ai[2 * i],     il[2 * i],     acc);
            erfc2_acc(ww.y, nm[2 * i + 1], ai[2 * i + 1], il[2 * i + 1], acc);
        }
    }

    float alo, ahi;
    unpk(acc, alo, ahi);
    float a = alo + ahi;
#pragma unroll
    for (int o = 16; o > 0; o >>= 1)
        a += __shfl_xor_sync(0xFFFFFFFFu, a, o);
    if (lane == 0) wsum[warp] = a;
    __syncthreads();

    if (threadIdx.x == 0) {
        float s = 0.0f;
#pragma unroll
        for (int i = 0; i < BT; i++) s += wsum[i];
        if (is_label_cta) s *= -2.0f;
        g_partials[blockIdx.y * (CBLK + 1) + blockIdx.x] = s;
    }
}

__global__ void finalize_kernel(float* __restrict__ out, int B, int C, int D) {
    __shared__ double dsum[8];
    double s = 0.0;
    for (int i = threadIdx.x; i < NPART; i += blockDim.x)
        s += (double)g_partials[i];
#pragma unroll
    for (int o = 16; o > 0; o >>= 1)
        s += __shfl_xor_sync(0xFFFFFFFFu, s, o);
    const int warp = threadIdx.x >> 5;
    const int lane = threadIdx.x & 31;
    if (lane == 0) dsum[warp] = s;
    __syncthreads();
    if (threadIdx.x == 0) {
        double t = 0.0;
        for (int i = 0; i < (int)(blockDim.x >> 5); i++) t += dsum[i];
        out[0] = (float)((t + 2.0 * (double)B * (double)D) / ((double)B * (double)C));
    }
}

extern "C" void kernel_launch(void* const* d_in, const int* in_sizes, int n_in,
                              void* d_out, int out_size) {
    const float* mu    = (const float*)d_in[0];
    const float* stdv  = (const float*)d_in[1];
    const float* w     = (const float*)d_in[2];
    const int*   label = (const int*)d_in[3];

    const int B = in_sizes[3];            // 128
    const int D = in_sizes[0] / B;        // 512
    const int C = in_sizes[2] / D;        // 1000

    dim3 grid(CBLK + 1, B / BT);          // (126, 16): 125 tile cols + 1 label col
    erfc_main_kernel<<<grid, BT * 32>>>(mu, stdv, w, label);

    finalize_kernel<<<1, 256>>>((float*)d_out, B, C, D);
}